// round 9
// baseline (speedup 1.0000x reference)
#include <cuda_runtime.h>
#include <cuda_bf16.h>
#include <cstdint>

// ---------------------------------------------------------------------------
// GIN encoder: 3 x (GINConv(sum-agg) -> MLP(64,relu,64) -> relu -> BN) -> add-pool
// Round 9: ncu showed k_mlp (68us/layer) L1-bound at 60% from smem staging.
// New k_mlp: NO shared memory, no syncthreads.
//   * W fragments preformatted in global (k_wprep) -> LDG.128 per kt (L1-hot)
//   * A fragments direct-LDG: k_agg writes packed bf16 hi/lo words in
//     m16n8k16 A-fragment word layout (word w = feats 2w,2w+1 of row)
//   * m16 x n64 warp tile: GEMM1 C-fragment layout == GEMM2 A-fragment layout
//     -> in-register repack, zero cross-thread traffic
//   * epilogue: shfl row-max, shfl-reduced BN stats -> global REDG,
//     u16-quantized feature output (as round 8; rel_err 1.28e-4 passed)
//   * gather stays u16+per-node scale (128B/edge); neighbor scales
//     pre-gathered once per warp and shuffled.
// ---------------------------------------------------------------------------

#define MAXN 131072
#define ELLW 64

__device__ int      g_cursor[MAXN];
__device__ int      g_ell[(size_t)MAXN * ELLW];
__device__ uint32_t g_qA[(size_t)MAXN * 32];   // packed u16x2 features
__device__ uint32_t g_qB[(size_t)MAXN * 32];
__device__ float    g_kA[MAXN];                // per-node decode scale s/32767
__device__ float    g_kB[MAXN];
__device__ uint32_t g_aggH[(size_t)MAXN * 32]; // agg, packed bf16 hi
__device__ uint32_t g_aggL[(size_t)MAXN * 32]; // agg, packed bf16 lo
__device__ float    g_stats[3 * 128];
__device__ float    g_coef[3 * 128];
// W fragments: [gemm 0..5][kt 0..3][lane 0..31][16 words]
__device__ __align__(16) uint32_t g_wfH[6 * 4 * 32 * 16];
__device__ __align__(16) uint32_t g_wfL[6 * 4 * 32 * 16];

// u16 decode: f = 2^23 + u (no CVT pipe)
__device__ __forceinline__ float dlo(uint32_t w) {
    return __uint_as_float(__byte_perm(w, 0x4B000000u, 0x7410));
}
__device__ __forceinline__ float dhi(uint32_t w) {
    return __uint_as_float(__byte_perm(w, 0x4B000000u, 0x7432));
}

// split (even,odd) floats into packed-bf16 hi word + lo word
// word layout: low half = even element (k even), high half = odd element
__device__ __forceinline__ void bf16split2(float ev, float od,
                                           uint32_t& hi, uint32_t& lo) {
    uint32_t h;
    asm("cvt.rn.bf16x2.f32 %0, %1, %2;" : "=r"(h) : "f"(od), "f"(ev));
    float fe = __uint_as_float(h << 16);
    float fo = __uint_as_float(h & 0xffff0000u);
    uint32_t l;
    asm("cvt.rn.bf16x2.f32 %0, %1, %2;" : "=r"(l) : "f"(od - fo), "f"(ev - fe));
    hi = h; lo = l;
}

__device__ __forceinline__ void mma_bf16(float c[4],
    uint32_t a0, uint32_t a1, uint32_t a2, uint32_t a3,
    uint32_t b0, uint32_t b1)
{
    asm volatile(
        "mma.sync.aligned.m16n8k16.row.col.f32.bf16.bf16.f32 "
        "{%0,%1,%2,%3}, {%4,%5,%6,%7}, {%8,%9}, {%0,%1,%2,%3};"
        : "+f"(c[0]), "+f"(c[1]), "+f"(c[2]), "+f"(c[3])
        : "r"(a0), "r"(a1), "r"(a2), "r"(a3), "r"(b0), "r"(b1));
}

// ---------------------------- W fragment preformat --------------------------
// 6 blocks (one per GEMM) x 128 threads (kt = t>>5, lane = t&31).
__global__ void k_wprep(const float* w1a, const float* w1b,
                        const float* w2a, const float* w2b,
                        const float* w3a, const float* w3b) {
    int gemm = blockIdx.x;
    const float* W = (gemm == 0) ? w1a : (gemm == 1) ? w1b :
                     (gemm == 2) ? w2a : (gemm == 3) ? w2b :
                     (gemm == 4) ? w3a : w3b;
    int t = threadIdx.x;
    int kt = t >> 5, lane = t & 31;
    int gid = lane >> 2, tig = lane & 3;
    int base = ((gemm * 4 + kt) * 32 + lane) * 16;
    int k0 = 16 * kt + 2 * tig;
#pragma unroll
    for (int j = 0; j < 4; j++) {
#pragma unroll
        for (int sub = 0; sub < 2; sub++) {
            int n = (2 * j + sub) * 8 + gid;
            uint32_t h0, l0, h1, l1;
            bf16split2(W[k0 * 64 + n],       W[(k0 + 1) * 64 + n], h0, l0);
            bf16split2(W[(k0 + 8) * 64 + n], W[(k0 + 9) * 64 + n], h1, l1);
            g_wfH[base + 4 * j + 2 * sub]     = h0;
            g_wfH[base + 4 * j + 2 * sub + 1] = h1;
            g_wfL[base + 4 * j + 2 * sub]     = l0;
            g_wfL[base + 4 * j + 2 * sub + 1] = l1;
        }
    }
}

// ---------------------------- prep (zero + quantize x) ----------------------
__global__ __launch_bounds__(256) void k_prep(const float* __restrict__ x, int N) {
    int gt = blockIdx.x * blockDim.x + threadIdx.x;
    if (gt < N)   g_cursor[gt] = 0;
    if (gt < 384) g_stats[gt]  = 0.f;
    int node = gt >> 5;
    int lane = gt & 31;
    if (node >= N) return;

    float2 v = ((const float2*)x)[(size_t)node * 32 + lane];
    float m = fmaxf(fabsf(v.x), fabsf(v.y));
#pragma unroll
    for (int o = 16; o > 0; o >>= 1)
        m = fmaxf(m, __shfl_xor_sync(0xffffffffu, m, o));
    float inv = (m > 0.f) ? (32767.f / m) : 0.f;
    if (lane == 0) g_kA[node] = m * (1.f / 32767.f);
    uint32_t u0 = __float2uint_rn(fmaf(v.x, inv, 32768.f));
    uint32_t u1 = __float2uint_rn(fmaf(v.y, inv, 32768.f));
    g_qA[(size_t)node * 32 + lane] = u0 | (u1 << 16);
}

// ---------------------------- ELL fill --------------------------------------
__global__ void k_fill(const int* __restrict__ src, const int* __restrict__ dst, int E) {
    int e = blockIdx.x * blockDim.x + threadIdx.x;
    if (e < E) {
        int d = dst[e];
        int p = atomicAdd(&g_cursor[d], 1);
        if (p < ELLW) g_ell[(size_t)d * ELLW + p] = src[e];
    }
}

// ---------------------------- aggregation -----------------------------------
// 1 warp/node; u16x2 per lane; fp32 accumulate; writes bf16 hi/lo packed words.
__global__ __launch_bounds__(256) void k_agg(int insel, int layer, int N)
{
    int gt   = blockIdx.x * blockDim.x + threadIdx.x;
    int node = gt >> 5;
    int lane = gt & 31;
    if (node >= N) return;

    const uint32_t* __restrict__ qin = (insel == 1) ? g_qA : g_qB;
    const float*    __restrict__ kin = (insel == 1) ? g_kA : g_kB;

    int deg = min(g_cursor[node], ELLW);
    const int* cols = g_ell + (size_t)node * ELLW;
    int c0 = cols[lane];
    int c1 = cols[lane + 32];
    float k0 = __ldg(&kin[c0]);      // indices always valid node ids
    float k1 = __ldg(&kin[c1]);

    // self term
    float kk = __ldg(&kin[node]);
    float sumk = kk;
    uint32_t w = qin[(size_t)node * 32 + lane];
    float cb = kk * -8388608.f;
    float ax = fmaf(dlo(w), kk, cb);
    float ay = fmaf(dhi(w), kk, cb);

    int d0 = min(deg, 32);
    int e = 0;
    for (; e + 3 < d0; e += 4) {
#pragma unroll
        for (int j = 0; j < 4; j++) {
            int   s  = __shfl_sync(0xffffffffu, c0, e + j);
            float ks = __shfl_sync(0xffffffffu, k0, e + j);
            uint32_t wd = qin[(size_t)s * 32 + lane];
            float cbe = ks * -8388608.f;
            sumk += ks;
            ax = fmaf(dlo(wd), ks, ax + cbe);
            ay = fmaf(dhi(wd), ks, ay + cbe);
        }
    }
    for (; e < d0; e++) {
        int   s  = __shfl_sync(0xffffffffu, c0, e);
        float ks = __shfl_sync(0xffffffffu, k0, e);
        uint32_t wd = qin[(size_t)s * 32 + lane];
        float cbe = ks * -8388608.f;
        sumk += ks;
        ax = fmaf(dlo(wd), ks, ax + cbe);
        ay = fmaf(dhi(wd), ks, ay + cbe);
    }
    int d1 = deg - 32;
    for (int e2 = 0; e2 < d1; e2++) {
        int   s  = __shfl_sync(0xffffffffu, c1, e2);
        float ks = __shfl_sync(0xffffffffu, k1, e2);
        uint32_t wd = qin[(size_t)s * 32 + lane];
        float cbe = ks * -8388608.f;
        sumk += ks;
        ax = fmaf(dlo(wd), ks, ax + cbe);
        ay = fmaf(dhi(wd), ks, ay + cbe);
    }

    // remove biased-u16 offsets
    ax = fmaf(sumk, -32768.f, ax);
    ay = fmaf(sumk, -32768.f, ay);

    if (layer > 0) {
        const float* cf = &g_coef[(layer - 1) * 128];
        float a0 = cf[2 * lane],      a1 = cf[2 * lane + 1];
        float b0 = cf[64 + 2 * lane], b1 = cf[65 + 2 * lane];
        float cnt = (float)(deg + 1);
        ax = a0 * ax + cnt * b0;
        ay = a1 * ay + cnt * b1;
    }
    uint32_t hw, lw;
    bf16split2(ax, ay, hw, lw);
    g_aggH[(size_t)node * 32 + lane] = hw;
    g_aggL[(size_t)node * 32 + lane] = lw;
}

// ---------------- smem-free bf16x3 tensor-core MLP ---------------------------
// 8 warps/block, each warp: 16 rows x full n=64. No smem, no syncthreads.
__global__ __launch_bounds__(256) void k_mlp(
    const float* __restrict__ ba, const float* __restrict__ bb,
    int outsel, int layer, int N)
{
    uint32_t* qout = (outsel == 1) ? g_qA : g_qB;
    float*    kout = (outsel == 1) ? g_kA : g_kB;

    int t = threadIdx.x;
    int lane = t & 31, w = t >> 5;
    int gid = lane >> 2, tig = lane & 3;
    int r0g = blockIdx.x * 128 + w * 16 + gid;  // rows: r0g (c0,c1), r0g+8 (c2,c3)
    int r1g = r0g + 8;

    const uint4* WH4 = (const uint4*)g_wfH;
    const uint4* WL4 = (const uint4*)g_wfL;
    int g1 = layer * 2, g2 = g1 + 1;

    float c[8][4];
#pragma unroll
    for (int nt = 0; nt < 8; nt++)
#pragma unroll
        for (int i = 0; i < 4; i++) c[nt][i] = 0.f;

    // ---- GEMM1: A from g_agg (direct fragment LDG), B from g_wf ----
#pragma unroll
    for (int kt = 0; kt < 4; kt++) {
        size_t ab = (size_t)r0g * 32 + kt * 8 + tig;
        uint32_t ah0 = g_aggH[ab],       ah2 = g_aggH[ab + 4];
        uint32_t ah1 = g_aggH[ab + 256], ah3 = g_aggH[ab + 260];
        uint32_t al0 = g_aggL[ab],       al2 = g_aggL[ab + 4];
        uint32_t al1 = g_aggL[ab + 256], al3 = g_aggL[ab + 260];
        int wb = ((g1 * 4 + kt) * 32 + lane) * 4;
#pragma unroll
        for (int j = 0; j < 4; j++) {
            uint4 bh = WH4[wb + j];
            uint4 bl = WL4[wb + j];
            mma_bf16(c[2 * j],     ah0, ah1, ah2, ah3, bh.x, bh.y);
            mma_bf16(c[2 * j],     ah0, ah1, ah2, ah3, bl.x, bl.y);
            mma_bf16(c[2 * j],     al0, al1, al2, al3, bh.x, bh.y);
            mma_bf16(c[2 * j + 1], ah0, ah1, ah2, ah3, bh.z, bh.w);
            mma_bf16(c[2 * j + 1], ah0, ah1, ah2, ah3, bl.z, bl.w);
            mma_bf16(c[2 * j + 1], al0, al1, al2, al3, bh.z, bh.w);
        }
    }

    // ---- bias1 + relu + in-register repack to GEMM2 A fragments ----
    uint32_t p0h[8], p0l[8], p1h[8], p1l[8];
#pragma unroll
    for (int nt = 0; nt < 8; nt++) {
        int col = nt * 8 + 2 * tig;
        float b0v = __ldg(ba + col), b1v = __ldg(ba + col + 1);
        float h0 = fmaxf(c[nt][0] + b0v, 0.f);
        float h1 = fmaxf(c[nt][1] + b1v, 0.f);
        float h2 = fmaxf(c[nt][2] + b0v, 0.f);
        float h3 = fmaxf(c[nt][3] + b1v, 0.f);
        bf16split2(h0, h1, p0h[nt], p0l[nt]);
        bf16split2(h2, h3, p1h[nt], p1l[nt]);
#pragma unroll
        for (int i = 0; i < 4; i++) c[nt][i] = 0.f;
    }

    // ---- GEMM2: A = repacked h (C-frag layout == A-frag layout) ----
#pragma unroll
    for (int kt = 0; kt < 4; kt++) {
        uint32_t ah0 = p0h[2 * kt],     ah1 = p1h[2 * kt];
        uint32_t ah2 = p0h[2 * kt + 1], ah3 = p1h[2 * kt + 1];
        uint32_t al0 = p0l[2 * kt],     al1 = p1l[2 * kt];
        uint32_t al2 = p0l[2 * kt + 1], al3 = p1l[2 * kt + 1];
        int wb = ((g2 * 4 + kt) * 32 + lane) * 4;
#pragma unroll
        for (int j = 0; j < 4; j++) {
            uint4 bh = WH4[wb + j];
            uint4 bl = WL4[wb + j];
            mma_bf16(c[2 * j],     ah0, ah1, ah2, ah3, bh.x, bh.y);
            mma_bf16(c[2 * j],     ah0, ah1, ah2, ah3, bl.x, bl.y);
            mma_bf16(c[2 * j],     al0, al1, al2, al3, bh.x, bh.y);
            mma_bf16(c[2 * j + 1], ah0, ah1, ah2, ah3, bh.z, bh.w);
            mma_bf16(c[2 * j + 1], ah0, ah1, ah2, ah3, bl.z, bl.w);
            mma_bf16(c[2 * j + 1], al0, al1, al2, al3, bh.z, bh.w);
        }
    }

    // ---- epilogue: bias2+relu (zero invalid rows), row max, stats, quant ----
    bool ok0 = r0g < N, ok1 = r1g < N;
    float mx0 = 0.f, mx1 = 0.f;
#pragma unroll
    for (int nt = 0; nt < 8; nt++) {
        int col = nt * 8 + 2 * tig;
        float b0v = __ldg(bb + col), b1v = __ldg(bb + col + 1);
        c[nt][0] = ok0 ? fmaxf(c[nt][0] + b0v, 0.f) : 0.f;
        c[nt][1] = ok0 ? fmaxf(c[nt][1] + b1v, 0.f) : 0.f;
        c[nt][2] = ok1 ? fmaxf(c[nt][2] + b0v, 0.f) : 0.f;
        c[nt][3] = ok1 ? fmaxf(c[nt][3] + b1v, 0.f) : 0.f;
        mx0 = fmaxf(mx0, fmaxf(c[nt][0], c[nt][1]));
        mx1 = fmaxf(mx1, fmaxf(c[nt][2], c[nt][3]));
    }
    mx0 = fmaxf(mx0, __shfl_xor_sync(0xffffffffu, mx0, 1));
    mx0 = fmaxf(mx0, __shfl_xor_sync(0xffffffffu, mx0, 2));
    mx1 = fmaxf(mx1, __shfl_xor_sync(0xffffffffu, mx1, 1));
    mx1 = fmaxf(mx1, __shfl_xor_sync(0xffffffffu, mx1, 2));

    // BN stats: per-column partials, reduce over gid (xor 4,8,16)
    float ss[16], qq[16];
#pragma unroll
    for (int nt = 0; nt < 8; nt++) {
        ss[2 * nt]     = c[nt][0] + c[nt][2];
        ss[2 * nt + 1] = c[nt][1] + c[nt][3];
        qq[2 * nt]     = c[nt][0] * c[nt][0] + c[nt][2] * c[nt][2];
        qq[2 * nt + 1] = c[nt][1] * c[nt][1] + c[nt][3] * c[nt][3];
    }
#pragma unroll
    for (int o = 4; o < 32; o <<= 1) {
#pragma unroll
        for (int i = 0; i < 16; i++) {
            ss[i] += __shfl_xor_sync(0xffffffffu, ss[i], o);
            qq[i] += __shfl_xor_sync(0xffffffffu, qq[i], o);
        }
    }
    if (gid == 0) {
#pragma unroll
        for (int nt = 0; nt < 8; nt++) {
            int col = nt * 8 + 2 * tig;
            atomicAdd(&g_stats[layer * 128 + col],          ss[2 * nt]);
            atomicAdd(&g_stats[layer * 128 + col + 1],      ss[2 * nt + 1]);
            atomicAdd(&g_stats[layer * 128 + 64 + col],     qq[2 * nt]);
            atomicAdd(&g_stats[layer * 128 + 64 + col + 1], qq[2 * nt + 1]);
        }
    }

    // quantize + store
    float inv0 = (mx0 > 0.f) ? (32767.f / mx0) : 0.f;
    float inv1 = (mx1 > 0.f) ? (32767.f / mx1) : 0.f;
    if (tig == 0 && ok0) kout[r0g] = mx0 * (1.f / 32767.f);
    if (tig == 0 && ok1) kout[r1g] = mx1 * (1.f / 32767.f);
#pragma unroll
    for (int nt = 0; nt < 8; nt++) {
        if (ok0) {
            uint32_t u0 = __float2uint_rn(fmaf(c[nt][0], inv0, 32768.f));
            uint32_t u1 = __float2uint_rn(fmaf(c[nt][1], inv0, 32768.f));
            qout[(size_t)r0g * 32 + 4 * nt + tig] = u0 | (u1 << 16);
        }
        if (ok1) {
            uint32_t u0 = __float2uint_rn(fmaf(c[nt][2], inv1, 32768.f));
            uint32_t u1 = __float2uint_rn(fmaf(c[nt][3], inv1, 32768.f));
            qout[(size_t)r1g * 32 + 4 * nt + tig] = u0 | (u1 << 16);
        }
    }
}

// ---------------------------- BN finalize -----------------------------------
__global__ void k_bnfin(const float* __restrict__ gamma,
                        const float* __restrict__ beta, int layer, int N) {
    int t = threadIdx.x;  // 64
    if (t >= 64) return;
    float invN = 1.f / (float)N;
    float mean = g_stats[layer * 128 + t] * invN;
    float var  = g_stats[layer * 128 + 64 + t] * invN - mean * mean;
    var = fmaxf(var, 0.f);
    float s = gamma[t] * rsqrtf(var + 1e-5f);
    g_coef[layer * 128 + t]      = s;
    g_coef[layer * 128 + 64 + t] = beta[t] - mean * s;
}

// ---------------------------- pool ------------------------------------------
__global__ void k_pool(int insel, const int* __restrict__ batch,
                       float* __restrict__ out, int N) {
    const uint32_t* q  = (insel == 1) ? g_qA : g_qB;
    const float*    kk = (insel == 1) ? g_kA : g_kB;
    const float* cf = &g_coef[2 * 128];
    int t   = threadIdx.x;  // 256
    int w   = t & 31;
    int sub = t >> 5;       // 0..7
    float a0 = cf[2 * w],      a1 = cf[2 * w + 1];
    float b0 = cf[64 + 2 * w], b1 = cf[65 + 2 * w];
    int n0  = blockIdx.x * 256;
    int nend = min(n0 + 256, N);
    float2 acc = make_float2(0.f, 0.f);
    int curg = -1;
    for (int n = n0 + sub; n < nend; n += 8) {
        int g = batch[n];
        if (g != curg) {
            if (curg >= 0) {
                atomicAdd(&out[curg * 64 + 2 * w],     acc.x);
                atomicAdd(&out[curg * 64 + 2 * w + 1], acc.y);
            }
            curg = g;
            acc = make_float2(0.f, 0.f);
        }
        float kn = kk[n];
        float cb = kn * -8388608.f;
        uint32_t wd = q[(size_t)n * 32 + w];
        float vx = fmaf(dlo(wd), kn, cb) - 32768.f * kn;
        float vy = fmaf(dhi(wd), kn, cb) - 32768.f * kn;
        acc.x += fmaf(a0, vx, b0);
        acc.y += fmaf(a1, vy, b1);
    }
    if (curg >= 0) {
        atomicAdd(&out[curg * 64 + 2 * w],     acc.x);
        atomicAdd(&out[curg * 64 + 2 * w + 1], acc.y);
    }
}

// ---------------------------- launch ----------------------------------------
extern "C" void kernel_launch(void* const* d_in, const int* in_sizes, int n_in,
                              void* d_out, int out_size) {
    const float* x     = (const float*)d_in[0];
    const int*   ei    = (const int*)d_in[1];
    const int*   batch = (const int*)d_in[2];

    const float* WA[3] = {(const float*)d_in[3],  (const float*)d_in[9],  (const float*)d_in[15]};
    const float* BA[3] = {(const float*)d_in[4],  (const float*)d_in[10], (const float*)d_in[16]};
    const float* WB[3] = {(const float*)d_in[5],  (const float*)d_in[11], (const float*)d_in[17]};
    const float* BB[3] = {(const float*)d_in[6],  (const float*)d_in[12], (const float*)d_in[18]};
    const float* GM[3] = {(const float*)d_in[7],  (const float*)d_in[13], (const float*)d_in[19]};
    const float* BE[3] = {(const float*)d_in[8],  (const float*)d_in[14], (const float*)d_in[20]};

    int N = in_sizes[0] / 64;
    int E = in_sizes[1] / 2;
    const int* src = ei;
    const int* dst = ei + E;

    // build: W fragments, zero + quantize x, ELL adjacency
    k_wprep<<<6, 128>>>(WA[0], WB[0], WA[1], WB[1], WA[2], WB[2]);
    k_prep<<<((size_t)N * 32 + 255) / 256, 256>>>(x, N);
    k_fill<<<(E + 255) / 256, 256>>>(src, dst, E);

    // 3 GIN layers
    int insel = 1;  // g_qA holds quantized x
    for (int L = 0; L < 3; L++) {
        int outsel = (L & 1) ? 1 : 2;  // L0->B, L1->A, L2->B
        k_agg<<<((size_t)N * 32 + 255) / 256, 256>>>(insel, L, N);
        k_mlp<<<(N + 127) / 128, 256>>>(BA[L], BB[L], outsel, L, N);
        k_bnfin<<<1, 64>>>(GM[L], BE[L], L, N);
        insel = outsel;
    }

    cudaMemsetAsync(d_out, 0, (size_t)out_size * sizeof(float));
    k_pool<<<(N + 255) / 256, 256>>>(insel, batch, (float*)d_out, N);
}

// round 10
// speedup vs baseline: 1.6874x; 1.6874x over previous
#include <cuda_runtime.h>
#include <cuda_bf16.h>
#include <cstdint>

// ---------------------------------------------------------------------------
// GIN encoder: 3 x (GINConv(sum-agg) -> MLP(64,relu,64) -> relu -> BN) -> add-pool
// Round 10: revert to round-6 structure (fp32 gather + smem bf16x3 MLP, best
// 311.8us) and cut k_mlp's smem instruction mill ~4x (round-8 ncu: L1 60%):
//   * uint2-packed (hi,lo) smem  -> STS.64/LDS.64, half the smem ops
//   * 4 tiles/block, W1+W2 staged ONCE per block (weights were 2/3 of traffic)
//     in 55KB dynamic smem
//   * BN stats in registers across tiles, one smem-atomic pass per block
//   * k_agg: fp32 float2 gather (round-9 u16 decode was issue-bound: ALU 43%)
//   * ELL adjacency (no scans), sorted-batch pool
// ---------------------------------------------------------------------------

#define MAXN 131072
#define ELLW 64
#define KP2  36                 // smem pitch in uint2 words
#define TPB  4                  // tiles (64 rows) per k_mlp block

__device__ int   g_cursor[MAXN];
__device__ int   g_ell[(size_t)MAXN * ELLW];
__device__ float g_rA[(size_t)MAXN * 64];
__device__ float g_rB[(size_t)MAXN * 64];
__device__ float g_agg[(size_t)MAXN * 64];
__device__ float g_stats[3 * 128];   // per layer: [0:64) sum, [64:128) sumsq
__device__ float g_coef[3 * 128];    // per layer: [0:64) scale a, [64:128) shift b

// split (ev,od) floats into packed-bf16 hi word (ev low half) + lo word
__device__ __forceinline__ void bf16split2(float ev, float od,
                                           uint32_t& hi, uint32_t& lo) {
    __nv_bfloat16 he = __float2bfloat16_rn(ev);
    __nv_bfloat16 ho = __float2bfloat16_rn(od);
    float le = ev - __bfloat162float(he);
    float lo_f = od - __bfloat162float(ho);
    __nv_bfloat162 ph, pl;
    ph.x = he; ph.y = ho;
    pl.x = __float2bfloat16_rn(le); pl.y = __float2bfloat16_rn(lo_f);
    hi = *(uint32_t*)&ph;
    lo = *(uint32_t*)&pl;
}

__device__ __forceinline__ void mma_bf16(float c[4],
    uint32_t a0, uint32_t a1, uint32_t a2, uint32_t a3,
    uint32_t b0, uint32_t b1)
{
    asm volatile(
        "mma.sync.aligned.m16n8k16.row.col.f32.bf16.bf16.f32 "
        "{%0,%1,%2,%3}, {%4,%5,%6,%7}, {%8,%9}, {%0,%1,%2,%3};"
        : "+f"(c[0]), "+f"(c[1]), "+f"(c[2]), "+f"(c[3])
        : "r"(a0), "r"(a1), "r"(a2), "r"(a3), "r"(b0), "r"(b1));
}

// ---------------------------- build ----------------------------------------

__global__ void k_zero(int N) {
    int i = blockIdx.x * blockDim.x + threadIdx.x;
    if (i < N)   g_cursor[i] = 0;
    if (i < 384) g_stats[i]  = 0.f;
}

__global__ void k_fill(const int* __restrict__ src, const int* __restrict__ dst, int E) {
    int e = blockIdx.x * blockDim.x + threadIdx.x;
    if (e < E) {
        int d = dst[e];
        int p = atomicAdd(&g_cursor[d], 1);
        if (p < ELLW) g_ell[(size_t)d * ELLW + p] = src[e];
    }
}

// ---------------------------- aggregation -----------------------------------
// 1 warp/node, float2/lane (256B/edge), ELL indices via coalesced load + shfl.
// Previous layer's BN affine folded in: a*(self+sum) + (deg+1)*b.
__global__ __launch_bounds__(256) void k_agg(
    const float* __restrict__ x, int insel /*0=x,1=rA,2=rB*/, int layer, int N)
{
    int gt   = blockIdx.x * blockDim.x + threadIdx.x;
    int node = gt >> 5;
    int lane = gt & 31;
    if (node >= N) return;

    const float2* __restrict__ inp =
        (insel == 0) ? (const float2*)x :
        (insel == 1) ? (const float2*)g_rA : (const float2*)g_rB;

    float2 acc = inp[(size_t)node * 32 + lane];   // self term
    int deg = min(g_cursor[node], ELLW);
    const int* cols = g_ell + (size_t)node * ELLW;
    int c0 = cols[lane];
    int c1 = cols[lane + 32];

    int d0 = min(deg, 32);
    int e = 0;
    for (; e + 3 < d0; e += 4) {
        int s0 = __shfl_sync(0xffffffffu, c0, e);
        int s1 = __shfl_sync(0xffffffffu, c0, e + 1);
        int s2 = __shfl_sync(0xffffffffu, c0, e + 2);
        int s3 = __shfl_sync(0xffffffffu, c0, e + 3);
        float2 v0 = inp[(size_t)s0 * 32 + lane];
        float2 v1 = inp[(size_t)s1 * 32 + lane];
        float2 v2 = inp[(size_t)s2 * 32 + lane];
        float2 v3 = inp[(size_t)s3 * 32 + lane];
        acc.x += (v0.x + v1.x) + (v2.x + v3.x);
        acc.y += (v0.y + v1.y) + (v2.y + v3.y);
    }
    for (; e < d0; e++) {
        int s = __shfl_sync(0xffffffffu, c0, e);
        float2 v = inp[(size_t)s * 32 + lane];
        acc.x += v.x;
        acc.y += v.y;
    }
    int d1 = deg - 32;
    for (int e2 = 0; e2 < d1; e2++) {
        int s = __shfl_sync(0xffffffffu, c1, e2);
        float2 v = inp[(size_t)s * 32 + lane];
        acc.x += v.x;
        acc.y += v.y;
    }

    if (layer > 0) {
        const float* cf = &g_coef[(layer - 1) * 128];
        float a0 = cf[2 * lane],      a1 = cf[2 * lane + 1];
        float b0 = cf[64 + 2 * lane], b1 = cf[65 + 2 * lane];
        float cnt = (float)(deg + 1);
        acc.x = a0 * acc.x + cnt * b0;
        acc.y = a1 * acc.y + cnt * b1;
    }
    ((float2*)g_agg)[(size_t)node * 32 + lane] = acc;
}

// ---------------- bf16x3 tensor-core MLP, multi-tile, uint2 smem ------------
// 256 threads (8 warps), TPB tiles of 64 rows. Warp tile m16 x n32.
// dyn smem: Q1[64][KP2] (W1, [n][kp]), Q2[64][KP2] (W2), P[64][KP2] (A / h).
__global__ __launch_bounds__(256) void k_mlp(
    const float* __restrict__ wa, const float* __restrict__ ba,
    const float* __restrict__ wb, const float* __restrict__ bb,
    int outsel /*1=rA,2=rB*/, int layer, int N)
{
    extern __shared__ uint2 dyn[];
    uint2* Q1 = dyn;
    uint2* Q2 = dyn + 64 * KP2;
    uint2* P  = dyn + 2 * 64 * KP2;
    __shared__ float B1s[64], B2s[64];
    __shared__ float ssum[64], ssq[64];

    float* rout = (outsel == 1) ? g_rA : g_rB;
    int t    = threadIdx.x;
    int lane = t & 31, warp = t >> 5;
    int gid  = lane >> 2, tig = lane & 3;
    int mi   = warp & 3,  ni  = warp >> 2;

    // stage W1 + W2 once per block
#pragma unroll
    for (int i = 0; i < 8; i++) {
        int idx = t + 256 * i;        // 0..2047
        int n = idx & 63, kp = idx >> 6;
        uint32_t hi, lo;
        bf16split2(wa[(2 * kp) * 64 + n], wa[(2 * kp + 1) * 64 + n], hi, lo);
        Q1[n * KP2 + kp] = make_uint2(hi, lo);
        bf16split2(wb[(2 * kp) * 64 + n], wb[(2 * kp + 1) * 64 + n], hi, lo);
        Q2[n * KP2 + kp] = make_uint2(hi, lo);
    }
    if (t < 64) { B1s[t] = ba[t]; B2s[t] = bb[t]; ssum[t] = 0.f; ssq[t] = 0.f; }
    __syncthreads();

    int aoff = (mi * 16 + gid) * KP2 + tig;
    int boff = (ni * 32 + gid) * KP2 + tig;

    // per-thread BN-stat accumulators across tiles (cols n0, n0+1 per nt)
    float ts[8], tq[8];
#pragma unroll
    for (int i = 0; i < 8; i++) { ts[i] = 0.f; tq[i] = 0.f; }

    int tile0 = blockIdx.x * TPB;
#pragma unroll 1
    for (int tile = 0; tile < TPB; tile++) {
        int m0 = (tile0 + tile) * 64;
        if (m0 >= N) break;

        // stage A tile from g_agg (coalesced float2 -> packed uint2)
#pragma unroll
        for (int i = 0; i < 8; i++) {
            int idx = t + 256 * i;
            int row = idx >> 5, w = idx & 31;
            int gm = m0 + row;
            float2 v = make_float2(0.f, 0.f);
            if (gm < N) v = ((const float2*)g_agg)[(size_t)gm * 32 + w];
            uint32_t hi, lo;
            bf16split2(v.x, v.y, hi, lo);
            P[row * KP2 + w] = make_uint2(hi, lo);
        }
        __syncthreads();

        float c[4][4];
#pragma unroll
        for (int nt = 0; nt < 4; nt++)
#pragma unroll
            for (int i = 0; i < 4; i++) c[nt][i] = 0.f;

        // GEMM1
#pragma unroll
        for (int kt = 0; kt < 4; kt++) {
            uint2 a0 = P[aoff + kt * 8];
            uint2 a1 = P[aoff + kt * 8 + 8 * KP2];
            uint2 a2 = P[aoff + kt * 8 + 4];
            uint2 a3 = P[aoff + kt * 8 + 8 * KP2 + 4];
#pragma unroll
            for (int nt = 0; nt < 4; nt++) {
                uint2 b0 = Q1[boff + nt * 8 * KP2 + kt * 8];
                uint2 b1 = Q1[boff + nt * 8 * KP2 + kt * 8 + 4];
                mma_bf16(c[nt], a0.x, a1.x, a2.x, a3.x, b0.x, b1.x);
                mma_bf16(c[nt], a0.x, a1.x, a2.x, a3.x, b0.y, b1.y);
                mma_bf16(c[nt], a0.y, a1.y, a2.y, a3.y, b0.x, b1.x);
            }
        }
        __syncthreads();   // all P reads (A) done

        // h = relu(c + b1) -> P
#pragma unroll
        for (int nt = 0; nt < 4; nt++) {
            int n0 = ni * 32 + nt * 8 + 2 * tig;
            float bb0 = B1s[n0], bb1 = B1s[n0 + 1];
            int r0 = mi * 16 + gid;
            int kp = n0 >> 1;
            uint32_t hi, lo;
            bf16split2(fmaxf(c[nt][0] + bb0, 0.f), fmaxf(c[nt][1] + bb1, 0.f), hi, lo);
            P[r0 * KP2 + kp] = make_uint2(hi, lo);
            bf16split2(fmaxf(c[nt][2] + bb0, 0.f), fmaxf(c[nt][3] + bb1, 0.f), hi, lo);
            P[(r0 + 8) * KP2 + kp] = make_uint2(hi, lo);
#pragma unroll
            for (int i = 0; i < 4; i++) c[nt][i] = 0.f;
        }
        __syncthreads();

        // GEMM2
#pragma unroll
        for (int kt = 0; kt < 4; kt++) {
            uint2 a0 = P[aoff + kt * 8];
            uint2 a1 = P[aoff + kt * 8 + 8 * KP2];
            uint2 a2 = P[aoff + kt * 8 + 4];
            uint2 a3 = P[aoff + kt * 8 + 8 * KP2 + 4];
#pragma unroll
            for (int nt = 0; nt < 4; nt++) {
                uint2 b0 = Q2[boff + nt * 8 * KP2 + kt * 8];
                uint2 b1 = Q2[boff + nt * 8 * KP2 + kt * 8 + 4];
                mma_bf16(c[nt], a0.x, a1.x, a2.x, a3.x, b0.x, b1.x);
                mma_bf16(c[nt], a0.x, a1.x, a2.x, a3.x, b0.y, b1.y);
                mma_bf16(c[nt], a0.y, a1.y, a2.y, a3.y, b0.x, b1.x);
            }
        }

        // epilogue: relu + bias2, store fp32, accumulate BN stats in registers
        int gr0 = m0 + mi * 16 + gid, gr1 = gr0 + 8;
        bool ok0 = gr0 < N, ok1 = gr1 < N;
#pragma unroll
        for (int nt = 0; nt < 4; nt++) {
            int n0 = ni * 32 + nt * 8 + 2 * tig;
            float bb0 = B2s[n0], bb1 = B2s[n0 + 1];
            float v00 = fmaxf(c[nt][0] + bb0, 0.f);
            float v01 = fmaxf(c[nt][1] + bb1, 0.f);
            float v10 = fmaxf(c[nt][2] + bb0, 0.f);
            float v11 = fmaxf(c[nt][3] + bb1, 0.f);
            if (ok0) {
                *(float2*)&rout[(size_t)gr0 * 64 + n0] = make_float2(v00, v01);
                ts[2 * nt]     += v00; tq[2 * nt]     += v00 * v00;
                ts[2 * nt + 1] += v01; tq[2 * nt + 1] += v01 * v01;
            }
            if (ok1) {
                *(float2*)&rout[(size_t)gr1 * 64 + n0] = make_float2(v10, v11);
                ts[2 * nt]     += v10; tq[2 * nt]     += v10 * v10;
                ts[2 * nt + 1] += v11; tq[2 * nt + 1] += v11 * v11;
            }
        }
        __syncthreads();   // P reads done before next tile restages
    }

    // one smem-atomic stats pass per block, then global flush
#pragma unroll
    for (int nt = 0; nt < 4; nt++) {
        int n0 = ni * 32 + nt * 8 + 2 * tig;
        atomicAdd(&ssum[n0],     ts[2 * nt]);
        atomicAdd(&ssq[n0],      tq[2 * nt]);
        atomicAdd(&ssum[n0 + 1], ts[2 * nt + 1]);
        atomicAdd(&ssq[n0 + 1],  tq[2 * nt + 1]);
    }
    __syncthreads();
    if (t < 64) {
        atomicAdd(&g_stats[layer * 128 + t],      ssum[t]);
        atomicAdd(&g_stats[layer * 128 + 64 + t], ssq[t]);
    }
}

// ---------------------------- BN finalize -----------------------------------
__global__ void k_bnfin(const float* __restrict__ gamma,
                        const float* __restrict__ beta, int layer, int N) {
    int t = threadIdx.x;  // 64
    if (t >= 64) return;
    float invN = 1.f / (float)N;
    float mean = g_stats[layer * 128 + t] * invN;
    float var  = g_stats[layer * 128 + 64 + t] * invN - mean * mean;
    var = fmaxf(var, 0.f);
    float s = gamma[t] * rsqrtf(var + 1e-5f);
    g_coef[layer * 128 + t]      = s;
    g_coef[layer * 128 + 64 + t] = beta[t] - mean * s;
}

// ---------------------------- pool ------------------------------------------
// batch sorted: run-length accumulate, atomics only at graph boundaries.
__global__ void k_pool(int insel /*1=rA,2=rB*/, const int* __restrict__ batch,
                       float* __restrict__ out, int N) {
    const float2* r = (insel == 1) ? (const float2*)g_rA : (const float2*)g_rB;
    const float* cf = &g_coef[2 * 128];
    int t   = threadIdx.x;  // 256
    int w   = t & 31;
    int sub = t >> 5;       // 0..7
    float a0 = cf[2 * w],      a1 = cf[2 * w + 1];
    float b0 = cf[64 + 2 * w], b1 = cf[65 + 2 * w];
    int n0  = blockIdx.x * 256;
    int nend = min(n0 + 256, N);
    float2 acc = make_float2(0.f, 0.f);
    int curg = -1;
    for (int n = n0 + sub; n < nend; n += 8) {
        int g = batch[n];
        if (g != curg) {
            if (curg >= 0) {
                atomicAdd(&out[curg * 64 + 2 * w],     acc.x);
                atomicAdd(&out[curg * 64 + 2 * w + 1], acc.y);
            }
            curg = g;
            acc = make_float2(0.f, 0.f);
        }
        float2 v = r[(size_t)n * 32 + w];
        acc.x += fmaf(a0, v.x, b0);
        acc.y += fmaf(a1, v.y, b1);
    }
    if (curg >= 0) {
        atomicAdd(&out[curg * 64 + 2 * w],     acc.x);
        atomicAdd(&out[curg * 64 + 2 * w + 1], acc.y);
    }
}

// ---------------------------- launch ----------------------------------------
extern "C" void kernel_launch(void* const* d_in, const int* in_sizes, int n_in,
                              void* d_out, int out_size) {
    const float* x     = (const float*)d_in[0];
    const int*   ei    = (const int*)d_in[1];
    const int*   batch = (const int*)d_in[2];

    const float* WA[3] = {(const float*)d_in[3],  (const float*)d_in[9],  (const float*)d_in[15]};
    const float* BA[3] = {(const float*)d_in[4],  (const float*)d_in[10], (const float*)d_in[16]};
    const float* WB[3] = {(const float*)d_in[5],  (const float*)d_in[11], (const float*)d_in[17]};
    const float* BB[3] = {(const float*)d_in[6],  (const float*)d_in[12], (const float*)d_in[18]};
    const float* GM[3] = {(const float*)d_in[7],  (const float*)d_in[13], (const float*)d_in[19]};
    const float* BE[3] = {(const float*)d_in[8],  (const float*)d_in[14], (const float*)d_in[20]};

    int N = in_sizes[0] / 64;
    int E = in_sizes[1] / 2;
    const int* src = ei;
    const int* dst = ei + E;

    const int DYN = 3 * 64 * KP2 * (int)sizeof(uint2);   // 55296 B
    cudaFuncSetAttribute(k_mlp, cudaFuncAttributeMaxDynamicSharedMemorySize, DYN);

    // build: zero cursor/stats, ELL adjacency
    k_zero<<<(N + 255) / 256, 256>>>(N);
    k_fill<<<(E + 255) / 256, 256>>>(src, dst, E);

    // 3 GIN layers
    int ntile = (N + 63) / 64;
    int mgrid = (ntile + TPB - 1) / TPB;
    int insel = 0;  // x
    for (int L = 0; L < 3; L++) {
        int outsel = (L & 1) ? 2 : 1;  // L0->rA, L1->rB, L2->rA
        k_agg<<<((size_t)N * 32 + 255) / 256, 256>>>(x, insel, L, N);
        k_mlp<<<mgrid, 256, DYN>>>(WA[L], BA[L], WB[L], BB[L], outsel, L, N);
        k_bnfin<<<1, 64>>>(GM[L], BE[L], L, N);
        insel = outsel;
    }

    cudaMemsetAsync(d_out, 0, (size_t)out_size * sizeof(float));
    k_pool<<<(N + 255) / 256, 256>>>(insel, batch, (float*)d_out, N);
}

// round 11
// speedup vs baseline: 1.7447x; 1.0339x over previous
#include <cuda_runtime.h>
#include <cuda_bf16.h>
#include <cstdint>

// ---------------------------------------------------------------------------
// GIN encoder: 3 x (GINConv(sum-agg) -> MLP(64,relu,64) -> relu -> BN) -> add-pool
// Round 11 (base: round-10 win, 271us). k_mlp was latency-bound (L1 49%,
// issue 42%, occ 31%, nothing saturated). Cuts:
//   * k_agg pre-splits agg to packed bf16 (hi,lo) uint2 -> g_aggP
//   * k_mlp stages A via cp.async (4x16B/thread): no LDG->convert->STS mill
//   * smem carveout 100% -> 3 blocks/SM (was 2)
//   * everything else: uint2 smem bf16x3 MMA, W staged once / 4 tiles,
//     BN stats in registers, ELL adjacency, sorted-batch pool.
// ---------------------------------------------------------------------------

#define MAXN 131072
#define ELLW 64
#define KP2  36                 // smem pitch in uint2 words
#define TPB  4                  // tiles (64 rows) per k_mlp block

__device__ int   g_cursor[MAXN];
__device__ int   g_ell[(size_t)MAXN * ELLW];
__device__ float g_rA[(size_t)MAXN * 64];
__device__ float g_rB[(size_t)MAXN * 64];
__device__ uint2 g_aggP[(size_t)MAXN * 32];   // packed bf16 (hi,lo) per k-pair
__device__ float g_stats[3 * 128];   // per layer: [0:64) sum, [64:128) sumsq
__device__ float g_coef[3 * 128];    // per layer: [0:64) scale a, [64:128) shift b

// split (ev,od) floats into packed-bf16 hi word (ev low half) + lo word
__device__ __forceinline__ void bf16split2(float ev, float od,
                                           uint32_t& hi, uint32_t& lo) {
    __nv_bfloat16 he = __float2bfloat16_rn(ev);
    __nv_bfloat16 ho = __float2bfloat16_rn(od);
    float le = ev - __bfloat162float(he);
    float lo_f = od - __bfloat162float(ho);
    __nv_bfloat162 ph, pl;
    ph.x = he; ph.y = ho;
    pl.x = __float2bfloat16_rn(le); pl.y = __float2bfloat16_rn(lo_f);
    hi = *(uint32_t*)&ph;
    lo = *(uint32_t*)&pl;
}

__device__ __forceinline__ void mma_bf16(float c[4],
    uint32_t a0, uint32_t a1, uint32_t a2, uint32_t a3,
    uint32_t b0, uint32_t b1)
{
    asm volatile(
        "mma.sync.aligned.m16n8k16.row.col.f32.bf16.bf16.f32 "
        "{%0,%1,%2,%3}, {%4,%5,%6,%7}, {%8,%9}, {%0,%1,%2,%3};"
        : "+f"(c[0]), "+f"(c[1]), "+f"(c[2]), "+f"(c[3])
        : "r"(a0), "r"(a1), "r"(a2), "r"(a3), "r"(b0), "r"(b1));
}

__device__ __forceinline__ void cp_async16(void* sdst, const void* gsrc) {
    uint32_t s = (uint32_t)__cvta_generic_to_shared(sdst);
    asm volatile("cp.async.cg.shared.global [%0], [%1], 16;" :: "r"(s), "l"(gsrc));
}

// ---------------------------- build ----------------------------------------

__global__ void k_zero(int N) {
    int i = blockIdx.x * blockDim.x + threadIdx.x;
    if (i < N)   g_cursor[i] = 0;
    if (i < 384) g_stats[i]  = 0.f;
}

__global__ void k_fill(const int* __restrict__ src, const int* __restrict__ dst, int E) {
    int e = blockIdx.x * blockDim.x + threadIdx.x;
    if (e < E) {
        int d = dst[e];
        int p = atomicAdd(&g_cursor[d], 1);
        if (p < ELLW) g_ell[(size_t)d * ELLW + p] = src[e];
    }
}

// ---------------------------- aggregation -----------------------------------
// 1 warp/node, float2/lane, ELL indices via coalesced load + shfl.
// Prev layer BN affine folded in; output = packed bf16 (hi,lo) A-tile words.
__global__ __launch_bounds__(256) void k_agg(
    const float* __restrict__ x, int insel /*0=x,1=rA,2=rB*/, int layer, int N)
{
    int gt   = blockIdx.x * blockDim.x + threadIdx.x;
    int node = gt >> 5;
    int lane = gt & 31;
    if (node >= N) return;

    const float2* __restrict__ inp =
        (insel == 0) ? (const float2*)x :
        (insel == 1) ? (const float2*)g_rA : (const float2*)g_rB;

    float2 acc = inp[(size_t)node * 32 + lane];   // self term
    int deg = min(g_cursor[node], ELLW);
    const int* cols = g_ell + (size_t)node * ELLW;
    int c0 = cols[lane];
    int c1 = cols[lane + 32];

    int d0 = min(deg, 32);
    int e = 0;
    for (; e + 3 < d0; e += 4) {
        int s0 = __shfl_sync(0xffffffffu, c0, e);
        int s1 = __shfl_sync(0xffffffffu, c0, e + 1);
        int s2 = __shfl_sync(0xffffffffu, c0, e + 2);
        int s3 = __shfl_sync(0xffffffffu, c0, e + 3);
        float2 v0 = inp[(size_t)s0 * 32 + lane];
        float2 v1 = inp[(size_t)s1 * 32 + lane];
        float2 v2 = inp[(size_t)s2 * 32 + lane];
        float2 v3 = inp[(size_t)s3 * 32 + lane];
        acc.x += (v0.x + v1.x) + (v2.x + v3.x);
        acc.y += (v0.y + v1.y) + (v2.y + v3.y);
    }
    for (; e < d0; e++) {
        int s = __shfl_sync(0xffffffffu, c0, e);
        float2 v = inp[(size_t)s * 32 + lane];
        acc.x += v.x;
        acc.y += v.y;
    }
    int d1 = deg - 32;
    for (int e2 = 0; e2 < d1; e2++) {
        int s = __shfl_sync(0xffffffffu, c1, e2);
        float2 v = inp[(size_t)s * 32 + lane];
        acc.x += v.x;
        acc.y += v.y;
    }

    if (layer > 0) {
        const float* cf = &g_coef[(layer - 1) * 128];
        float a0 = cf[2 * lane],      a1 = cf[2 * lane + 1];
        float b0 = cf[64 + 2 * lane], b1 = cf[65 + 2 * lane];
        float cnt = (float)(deg + 1);
        acc.x = a0 * acc.x + cnt * b0;
        acc.y = a1 * acc.y + cnt * b1;
    }
    uint32_t hi, lo;
    bf16split2(acc.x, acc.y, hi, lo);
    g_aggP[(size_t)node * 32 + lane] = make_uint2(hi, lo);
}

// ---------------- bf16x3 tensor-core MLP, multi-tile, cp.async A -----------
// 256 threads (8 warps), TPB tiles of 64 rows. Warp tile m16 x n32.
// dyn smem: Q1[64][KP2] (W1, [n][kp]), Q2[64][KP2] (W2), P[64][KP2] (A / h).
__global__ __launch_bounds__(256) void k_mlp(
    const float* __restrict__ wa, const float* __restrict__ ba,
    const float* __restrict__ wb, const float* __restrict__ bb,
    int outsel /*1=rA,2=rB*/, int layer, int N)
{
    extern __shared__ uint2 dyn[];
    uint2* Q1 = dyn;
    uint2* Q2 = dyn + 64 * KP2;
    uint2* P  = dyn + 2 * 64 * KP2;
    __shared__ float B1s[64], B2s[64];
    __shared__ float ssum[64], ssq[64];

    float* rout = (outsel == 1) ? g_rA : g_rB;
    int t    = threadIdx.x;
    int lane = t & 31, warp = t >> 5;
    int gid  = lane >> 2, tig = lane & 3;
    int mi   = warp & 3,  ni  = warp >> 2;

    // stage W1 + W2 once per block
#pragma unroll
    for (int i = 0; i < 8; i++) {
        int idx = t + 256 * i;        // 0..2047
        int n = idx & 63, kp = idx >> 6;
        uint32_t hi, lo;
        bf16split2(wa[(2 * kp) * 64 + n], wa[(2 * kp + 1) * 64 + n], hi, lo);
        Q1[n * KP2 + kp] = make_uint2(hi, lo);
        bf16split2(wb[(2 * kp) * 64 + n], wb[(2 * kp + 1) * 64 + n], hi, lo);
        Q2[n * KP2 + kp] = make_uint2(hi, lo);
    }
    if (t < 64) { B1s[t] = ba[t]; B2s[t] = bb[t]; ssum[t] = 0.f; ssq[t] = 0.f; }
    __syncthreads();

    int aoff = (mi * 16 + gid) * KP2 + tig;
    int boff = (ni * 32 + gid) * KP2 + tig;

    // per-thread BN-stat accumulators across tiles
    float ts[8], tq[8];
#pragma unroll
    for (int i = 0; i < 8; i++) { ts[i] = 0.f; tq[i] = 0.f; }

    int tile0 = blockIdx.x * TPB;
#pragma unroll 1
    for (int tile = 0; tile < TPB; tile++) {
        int m0 = (tile0 + tile) * 64;
        if (m0 >= N) break;

        // stage A tile via cp.async: 1024 16B chunks (2 uint2 each)
#pragma unroll
        for (int j = 0; j < 4; j++) {
            int idx = t + 256 * j;         // 0..1023
            int row = idx >> 4;
            int cp  = (idx & 15) * 2;      // uint2 pair index
            cp_async16(&P[row * KP2 + cp], &g_aggP[(size_t)(m0 + row) * 32 + cp]);
        }
        asm volatile("cp.async.commit_group;");
        asm volatile("cp.async.wait_group 0;" ::: "memory");
        __syncthreads();

        float c[4][4];
#pragma unroll
        for (int nt = 0; nt < 4; nt++)
#pragma unroll
            for (int i = 0; i < 4; i++) c[nt][i] = 0.f;

        // GEMM1
#pragma unroll
        for (int kt = 0; kt < 4; kt++) {
            uint2 a0 = P[aoff + kt * 8];
            uint2 a1 = P[aoff + kt * 8 + 8 * KP2];
            uint2 a2 = P[aoff + kt * 8 + 4];
            uint2 a3 = P[aoff + kt * 8 + 8 * KP2 + 4];
#pragma unroll
            for (int nt = 0; nt < 4; nt++) {
                uint2 b0 = Q1[boff + nt * 8 * KP2 + kt * 8];
                uint2 b1 = Q1[boff + nt * 8 * KP2 + kt * 8 + 4];
                mma_bf16(c[nt], a0.x, a1.x, a2.x, a3.x, b0.x, b1.x);
                mma_bf16(c[nt], a0.x, a1.x, a2.x, a3.x, b0.y, b1.y);
                mma_bf16(c[nt], a0.y, a1.y, a2.y, a3.y, b0.x, b1.x);
            }
        }
        __syncthreads();   // all P reads (A) done

        // h = relu(c + b1) -> P
#pragma unroll
        for (int nt = 0; nt < 4; nt++) {
            int n0 = ni * 32 + nt * 8 + 2 * tig;
            float bb0 = B1s[n0], bb1 = B1s[n0 + 1];
            int r0 = mi * 16 + gid;
            int kp = n0 >> 1;
            uint32_t hi, lo;
            bf16split2(fmaxf(c[nt][0] + bb0, 0.f), fmaxf(c[nt][1] + bb1, 0.f), hi, lo);
            P[r0 * KP2 + kp] = make_uint2(hi, lo);
            bf16split2(fmaxf(c[nt][2] + bb0, 0.f), fmaxf(c[nt][3] + bb1, 0.f), hi, lo);
            P[(r0 + 8) * KP2 + kp] = make_uint2(hi, lo);
#pragma unroll
            for (int i = 0; i < 4; i++) c[nt][i] = 0.f;
        }
        __syncthreads();

        // GEMM2
#pragma unroll
        for (int kt = 0; kt < 4; kt++) {
            uint2 a0 = P[aoff + kt * 8];
            uint2 a1 = P[aoff + kt * 8 + 8 * KP2];
            uint2 a2 = P[aoff + kt * 8 + 4];
            uint2 a3 = P[aoff + kt * 8 + 8 * KP2 + 4];
#pragma unroll
            for (int nt = 0; nt < 4; nt++) {
                uint2 b0 = Q2[boff + nt * 8 * KP2 + kt * 8];
                uint2 b1 = Q2[boff + nt * 8 * KP2 + kt * 8 + 4];
                mma_bf16(c[nt], a0.x, a1.x, a2.x, a3.x, b0.x, b1.x);
                mma_bf16(c[nt], a0.x, a1.x, a2.x, a3.x, b0.y, b1.y);
                mma_bf16(c[nt], a0.y, a1.y, a2.y, a3.y, b0.x, b1.x);
            }
        }

        // epilogue: relu + bias2, store fp32, accumulate BN stats in registers
        int gr0 = m0 + mi * 16 + gid, gr1 = gr0 + 8;
        bool ok0 = gr0 < N, ok1 = gr1 < N;
#pragma unroll
        for (int nt = 0; nt < 4; nt++) {
            int n0 = ni * 32 + nt * 8 + 2 * tig;
            float bb0 = B2s[n0], bb1 = B2s[n0 + 1];
            float v00 = fmaxf(c[nt][0] + bb0, 0.f);
            float v01 = fmaxf(c[nt][1] + bb1, 0.f);
            float v10 = fmaxf(c[nt][2] + bb0, 0.f);
            float v11 = fmaxf(c[nt][3] + bb1, 0.f);
            if (ok0) {
                *(float2*)&rout[(size_t)gr0 * 64 + n0] = make_float2(v00, v01);
                ts[2 * nt]     += v00; tq[2 * nt]     += v00 * v00;
                ts[2 * nt + 1] += v01; tq[2 * nt + 1] += v01 * v01;
            }
            if (ok1) {
                *(float2*)&rout[(size_t)gr1 * 64 + n0] = make_float2(v10, v11);
                ts[2 * nt]     += v10; tq[2 * nt]     += v10 * v10;
                ts[2 * nt + 1] += v11; tq[2 * nt + 1] += v11 * v11;
            }
        }
        __syncthreads();   // P reads done before next tile restages
    }

    // one smem-atomic stats pass per block, then global flush
#pragma unroll
    for (int nt = 0; nt < 4; nt++) {
        int n0 = ni * 32 + nt * 8 + 2 * tig;
        atomicAdd(&ssum[n0],     ts[2 * nt]);
        atomicAdd(&ssq[n0],      tq[2 * nt]);
        atomicAdd(&ssum[n0 + 1], ts[2 * nt + 1]);
        atomicAdd(&ssq[n0 + 1],  tq[2 * nt + 1]);
    }
    __syncthreads();
    if (t < 64) {
        atomicAdd(&g_stats[layer * 128 + t],      ssum[t]);
        atomicAdd(&g_stats[layer * 128 + 64 + t], ssq[t]);
    }
}

// ---------------------------- BN finalize -----------------------------------
__global__ void k_bnfin(const float* __restrict__ gamma,
                        const float* __restrict__ beta, int layer, int N) {
    int t = threadIdx.x;  // 64
    if (t >= 64) return;
    float invN = 1.f / (float)N;
    float mean = g_stats[layer * 128 + t] * invN;
    float var  = g_stats[layer * 128 + 64 + t] * invN - mean * mean;
    var = fmaxf(var, 0.f);
    float s = gamma[t] * rsqrtf(var + 1e-5f);
    g_coef[layer * 128 + t]      = s;
    g_coef[layer * 128 + 64 + t] = beta[t] - mean * s;
}

// ---------------------------- pool ------------------------------------------
// batch sorted: run-length accumulate, atomics only at graph boundaries.
__global__ void k_pool(int insel /*1=rA,2=rB*/, const int* __restrict__ batch,
                       float* __restrict__ out, int N) {
    const float2* r = (insel == 1) ? (const float2*)g_rA : (const float2*)g_rB;
    const float* cf = &g_coef[2 * 128];
    int t   = threadIdx.x;  // 256
    int w   = t & 31;
    int sub = t >> 5;       // 0..7
    float a0 = cf[2 * w],      a1 = cf[2 * w + 1];
    float b0 = cf[64 + 2 * w], b1 = cf[65 + 2 * w];
    int n0  = blockIdx.x * 256;
    int nend = min(n0 + 256, N);
    float2 acc = make_float2(0.f, 0.f);
    int curg = -1;
    for (int n = n0 + sub; n < nend; n += 8) {
        int g = batch[n];
        if (g != curg) {
            if (curg >= 0) {
                atomicAdd(&out[curg * 64 + 2 * w],     acc.x);
                atomicAdd(&out[curg * 64 + 2 * w + 1], acc.y);
            }
            curg = g;
            acc = make_float2(0.f, 0.f);
        }
        float2 v = r[(size_t)n * 32 + w];
        acc.x += fmaf(a0, v.x, b0);
        acc.y += fmaf(a1, v.y, b1);
    }
    if (curg >= 0) {
        atomicAdd(&out[curg * 64 + 2 * w],     acc.x);
        atomicAdd(&out[curg * 64 + 2 * w + 1], acc.y);
    }
}

// ---------------------------- launch ----------------------------------------
extern "C" void kernel_launch(void* const* d_in, const int* in_sizes, int n_in,
                              void* d_out, int out_size) {
    const float* x     = (const float*)d_in[0];
    const int*   ei    = (const int*)d_in[1];
    const int*   batch = (const int*)d_in[2];

    const float* WA[3] = {(const float*)d_in[3],  (const float*)d_in[9],  (const float*)d_in[15]};
    const float* BA[3] = {(const float*)d_in[4],  (const float*)d_in[10], (const float*)d_in[16]};
    const float* WB[3] = {(const float*)d_in[5],  (const float*)d_in[11], (const float*)d_in[17]};
    const float* BB[3] = {(const float*)d_in[6],  (const float*)d_in[12], (const float*)d_in[18]};
    const float* GM[3] = {(const float*)d_in[7],  (const float*)d_in[13], (const float*)d_in[19]};
    const float* BE[3] = {(const float*)d_in[8],  (const float*)d_in[14], (const float*)d_in[20]};

    int N = in_sizes[0] / 64;
    int E = in_sizes[1] / 2;
    const int* src = ei;
    const int* dst = ei + E;

    const int DYN = 3 * 64 * KP2 * (int)sizeof(uint2);   // 55296 B
    cudaFuncSetAttribute(k_mlp, cudaFuncAttributeMaxDynamicSharedMemorySize, DYN);
    cudaFuncSetAttribute(k_mlp, cudaFuncAttributePreferredSharedMemoryCarveout, 100);

    // build: zero cursor/stats, ELL adjacency
    k_zero<<<(N + 255) / 256, 256>>>(N);
    k_fill<<<(E + 255) / 256, 256>>>(src, dst, E);

    // 3 GIN layers
    int ntile = (N + 63) / 64;
    int mgrid = (ntile + TPB - 1) / TPB;
    int insel = 0;  // x
    for (int L = 0; L < 3; L++) {
        int outsel = (L & 1) ? 2 : 1;  // L0->rA, L1->rB, L2->rA
        k_agg<<<((size_t)N * 32 + 255) / 256, 256>>>(x, insel, L, N);
        k_mlp<<<mgrid, 256, DYN>>>(WA[L], BA[L], WB[L], BB[L], outsel, L, N);
        k_bnfin<<<1, 64>>>(GM[L], BE[L], L, N);
        insel = outsel;
    }

    cudaMemsetAsync(d_out, 0, (size_t)out_size * sizeof(float));
    k_pool<<<(N + 255) / 256, 256>>>(insel, batch, (float*)d_out, N);
}